// round 14
// baseline (speedup 1.0000x reference)
#include <cuda_runtime.h>

#define NB 64
#define NN 1024
#define NWORDS 32          // NN/32 bitmask words per node row
#define NITER 5
#define NT 512             // threads per block; each owns 2 elements

// scratch (no allocations allowed)
__device__ float    g_feats[NB * NN];  // per-graph label histograms (6 stages)
__device__ float    g_dnorm[NB];       // sqrt(dot(feats_b, feats_b))
__device__ unsigned g_bar;             // monotonic grid-barrier ticket counter

// compare-exchange
__device__ __forceinline__ unsigned cex(unsigned a, unsigned b, bool keep_min)
{
    unsigned mn = a < b ? a : b;
    unsigned mx = a < b ? b : a;
    return keep_min ? mn : mx;
}

// one bitonic stage (merge size k, distance j) for network position pos
__device__ __forceinline__ unsigned stage_single(const unsigned* in, int pos, int k, int j)
{
    bool asc = ((pos & k) == 0);
    return cex(in[pos], in[pos ^ j], (((pos & j) == 0) == asc));
}

// two consecutive stages (j1 then j2=j1/2) fused: 4 reads, 3 cex.
__device__ __forceinline__ unsigned stage_pair(const unsigned* in, int pos, int k, int j1, int j2)
{
    bool asc = ((pos & k) == 0);
    bool km1 = (((pos & j1) == 0) == asc);
    unsigned a  = cex(in[pos],      in[pos ^ j1],        km1);
    unsigned bb = cex(in[pos ^ j2], in[(pos ^ j2) ^ j1], km1);
    return cex(a, bb, (((pos & j2) == 0) == asc));
}

// intra-warp bitonic merge: predicates from pos, shuffles on lane (pos&31)
__device__ __forceinline__ unsigned warp_merge32(unsigned v, int pos, int k, int jstart)
{
    bool dir = ((pos & k) == 0);
    #pragma unroll
    for (int j = jstart; j > 0; j >>= 1) {
        unsigned o = __shfl_xor_sync(0xffffffffu, v, j);
        bool keep_min = (((pos & j) == 0) == dir);
        unsigned mn = v < o ? v : o;
        unsigned mx = v < o ? o : v;
        v = keep_min ? mn : mx;
    }
    return v;
}

// -------------------------------------------------------------------------
// FUSED kernel: one block per graph, 512 threads, 2 elements/thread.
// Dynamic SMEM (217088 B, opt-in):
//   [0      , 131072) : unsigned smask[32768]   adjacency bits
//   [131072 , 196608) : u16 s_ent[32768]        CSR entries (even-aligned runs)
//   [196608 , 200704) : int s_lab[1024]         labels
//   [200704 , 204800) : int s_cnt[1024]         histogram counts
//   [204800 , 208896) : unsigned s_keyA[1024]   sort ping buffer (gram: sf)
//   [208896 , 212992) : unsigned s_keyB[1024]   sort pong buffer (run-pos)
//   [212992 , 217088) : int s_scan[1024]        rank per sorted position
// -------------------------------------------------------------------------
extern "C" __global__ void __launch_bounds__(NT, 1)
wl_fused_kernel(const int* __restrict__ esrc, const int* __restrict__ edst,
                const int* __restrict__ labels0, const float* __restrict__ hw,
                int E, float* __restrict__ out)
{
    extern __shared__ unsigned char s_raw[];
    unsigned*       smask  = (unsigned*)s_raw;                  // 128KB
    unsigned short* s_ent  = (unsigned short*)(s_raw + 131072); // 64KB
    int*            s_lab  = (int*)(s_raw + 196608);            // 4KB
    int*            s_cnt  = (int*)(s_raw + 200704);            // 4KB
    unsigned*       s_keyA = (unsigned*)(s_raw + 204800);       // 4KB
    unsigned*       s_keyB = (unsigned*)(s_raw + 208896);       // 4KB
    int*            s_scan = (int*)(s_raw + 212992);            // 4KB
    __shared__ int s_warp[32];
    __shared__ int s_R;

    const int t    = threadIdx.x;     // 0..511
    const int p1   = t + NT;          // second owned position/node
    const int b    = blockIdx.x;
    const int lane = t & 31;
    const int wid  = t >> 5;          // 0..15
    const float w0 = hw[0], w1 = hw[1];

    // --- zero mask + counts (64 words/thread) ---
    #pragma unroll
    for (int w = 0; w < 64; w++) smask[t + w * NT] = 0u;
    s_cnt[t] = 0; s_cnt[p1] = 0;
    __syncthreads();

    // --- build directed adjacency bitmask (atomicOr dedupes edges) ---
    if ((E & 3) == 0) {
        const int4* s4 = (const int4*)(esrc + (size_t)b * E);
        const int4* d4 = (const int4*)(edst + (size_t)b * E);
        const int n4 = E >> 2;
        for (int i = t; i < n4; i += NT) {
            int4 s = s4[i];
            int4 d = d4[i];
            atomicOr(&smask[(s.x << 5) + (d.x >> 5)], 1u << (d.x & 31));
            atomicOr(&smask[(s.y << 5) + (d.y >> 5)], 1u << (d.y & 31));
            atomicOr(&smask[(s.z << 5) + (d.z >> 5)], 1u << (d.z & 31));
            atomicOr(&smask[(s.w << 5) + (d.w >> 5)], 1u << (d.w & 31));
        }
    } else {
        for (int e = t; e < E; e += NT) {
            int s = esrc[b * E + e];
            int d = edst[b * E + e];
            atomicOr(&smask[(s << 5) + (d >> 5)], 1u << (d & 31));
        }
    }

    // --- initial labels + stage-0 histogram (warp-aggregated atomics) ---
    int mylab0 = labels0[b * NN + t];
    int mylab1 = labels0[b * NN + p1];
    s_lab[t]  = mylab0;
    s_lab[p1] = mylab1;
    {
        unsigned pe = __match_any_sync(0xffffffffu, mylab0);
        if (lane == __ffs(pe) - 1) atomicAdd(&s_cnt[mylab0], __popc(pe));
        pe = __match_any_sync(0xffffffffu, mylab1);
        if (lane == __ffs(pe) - 1) atomicAdd(&s_cnt[mylab1], __popc(pe));
    }
    __syncthreads();

    // --- degrees (staggered word order) ---
    int deg0 = 0, deg1 = 0;
    #pragma unroll
    for (int wi = 0; wi < NWORDS; wi++) {
        int w = (wi + t) & 31;
        deg0 += __popc(smask[(t  << 5) + w]);
        deg1 += __popc(smask[(p1 << 5) + w]);
    }
    const int degPad0 = (deg0 + 1) & ~1;
    const int degPad1 = (deg1 + 1) & ~1;
    const int dp = degPad0 + degPad1;

    // --- K = max degree, exclusive scan of dp -> even CSR offsets ---
    int kv = max(deg0, deg1);
    #pragma unroll
    for (int o = 16; o > 0; o >>= 1) kv = max(kv, __shfl_xor_sync(0xffffffffu, kv, o));
    int incl = dp;
    #pragma unroll
    for (int o = 1; o < 32; o <<= 1) {
        int n = __shfl_up_sync(0xffffffffu, incl, o);
        if (lane >= o) incl += n;
    }
    if (lane == 31) { s_warp[wid] = incl; s_scan[wid] = kv; }
    __syncthreads();
    int wpre, K;
    {
        int x = (lane < 16) ? s_warp[lane] : 0;
        int xm = (lane < wid) ? x : 0;
        #pragma unroll
        for (int o = 16; o > 0; o >>= 1) xm += __shfl_xor_sync(0xffffffffu, xm, o);
        wpre = xm;
        int m = (lane < 16) ? s_scan[lane] : 0;
        #pragma unroll
        for (int o = 16; o > 0; o >>= 1) m = max(m, __shfl_xor_sync(0xffffffffu, m, o));
        K = m;
    }
    const int off0 = wpre + incl - dp;      // even
    const int off1 = off0 + degPad0;        // even
    __syncthreads();

    // --- build CSR u16 neighbor entries (once) ---
    {
        int p = off0;
        #pragma unroll
        for (int w = 0; w < NWORDS; w++) {
            unsigned m = smask[(t << 5) + w];
            int base = w << 5;
            while (m) { int bb = __ffs(m) - 1; m &= m - 1; s_ent[p++] = (unsigned short)(base + bb); }
        }
        p = off1;
        #pragma unroll
        for (int w = 0; w < NWORDS; w++) {
            unsigned m = smask[(p1 << 5) + w];
            int base = w << 5;
            while (m) { int bb = __ffs(m) - 1; m &= m - 1; s_ent[p++] = (unsigned short)(base + bb); }
        }
    }
    __syncthreads();

    const float Kw0 = __fmul_rn((float)K, w0);
    const unsigned* e32base = (const unsigned*)s_ent;

    for (int it = 0; it < NITER; it++) {
        // --- seg gathers for both nodes (u32-packed, 2 independent chains) ---
        int seg0 = 0, seg1 = 0;
        {
            const unsigned* e32 = e32base + (off0 >> 1);
            const int nf = deg0 >> 1;
            #pragma unroll 4
            for (int n = 0; n < nf; n++) {
                unsigned e = e32[n];
                seg0 += s_lab[e & 0xFFFFu] + s_lab[e >> 16];
            }
            if (deg0 & 1) seg0 += s_lab[s_ent[off0 + deg0 - 1]];
        }
        {
            const unsigned* e32 = e32base + (off1 >> 1);
            const int nf = deg1 >> 1;
            #pragma unroll 4
            for (int n = 0; n < nf; n++) {
                unsigned e = e32[n];
                seg1 += s_lab[e & 0xFFFFu] + s_lab[e >> 16];
            }
            if (deg1 & 1) seg1 += s_lab[s_ent[off1 + deg1 - 1]];
        }

        // --- hashes (exact-int args; no FMA contraction; -0 canonicalized) ---
        float h0 = __fadd_rn(__fmul_rn(Kw0, (float)mylab0),
                             __fmul_rn(w1, (float)(seg0 + deg0 - K)));
        float h1 = __fadd_rn(__fmul_rn(Kw0, (float)mylab1),
                             __fmul_rn(w1, (float)(seg1 + deg1 - K)));
        h0 = __fadd_rn(h0, 0.0f);
        h1 = __fadd_rn(h1, 0.0f);
        unsigned u0 = __float_as_uint(h0);
        unsigned u1 = __float_as_uint(h1);
        u0 = (u0 & 0x80000000u) ? ~u0 : (u0 | 0x80000000u);
        u1 = (u1 & 0x80000000u) ? ~u1 : (u1 | 0x80000000u);
        const unsigned mykey0 = u0, mykey1 = u1;
        unsigned v0 = u0, v1 = u1;

        // --- warp phase: k = 2..32 (two independent chains) ---
        #pragma unroll
        for (int k = 2; k <= 32; k <<= 1) {
            v0 = warp_merge32(v0, t,  k, k >> 1);
            v1 = warp_merge32(v1, p1, k, k >> 1);
        }

        unsigned* cur = s_keyA;
        unsigned* nxt = s_keyB;
        cur[t] = v0; cur[p1] = v1;
        __syncthreads();

        // --- k=64 ---
        v0 = stage_single(cur, t,  64, 32); v0 = warp_merge32(v0, t,  64, 16);
        v1 = stage_single(cur, p1, 64, 32); v1 = warp_merge32(v1, p1, 64, 16);
        nxt[t] = v0; nxt[p1] = v1; { unsigned* tm = cur; cur = nxt; nxt = tm; }
        __syncthreads();

        // --- k=128 ---
        v0 = stage_pair(cur, t,  128, 64, 32); v0 = warp_merge32(v0, t,  128, 16);
        v1 = stage_pair(cur, p1, 128, 64, 32); v1 = warp_merge32(v1, p1, 128, 16);
        nxt[t] = v0; nxt[p1] = v1; { unsigned* tm = cur; cur = nxt; nxt = tm; }
        __syncthreads();

        // --- k=256 ---
        v0 = stage_pair(cur, t,  256, 128, 64);
        v1 = stage_pair(cur, p1, 256, 128, 64);
        nxt[t] = v0; nxt[p1] = v1; { unsigned* tm = cur; cur = nxt; nxt = tm; }
        __syncthreads();
        v0 = stage_single(cur, t,  256, 32); v0 = warp_merge32(v0, t,  256, 16);
        v1 = stage_single(cur, p1, 256, 32); v1 = warp_merge32(v1, p1, 256, 16);
        nxt[t] = v0; nxt[p1] = v1; { unsigned* tm = cur; cur = nxt; nxt = tm; }
        __syncthreads();

        // --- k=512 ---
        v0 = stage_pair(cur, t,  512, 256, 128);
        v1 = stage_pair(cur, p1, 512, 256, 128);
        nxt[t] = v0; nxt[p1] = v1; { unsigned* tm = cur; cur = nxt; nxt = tm; }
        __syncthreads();
        v0 = stage_pair(cur, t,  512, 64, 32); v0 = warp_merge32(v0, t,  512, 16);
        v1 = stage_pair(cur, p1, 512, 64, 32); v1 = warp_merge32(v1, p1, 512, 16);
        // k=1024, j=512 stage in REGISTERS: partner of pos t is pos t+512,
        // both owned. All-ascending (k=1024): v0 <- min, v1 <- max.
        {
            unsigned mn = v0 < v1 ? v0 : v1;
            unsigned mx = v0 < v1 ? v1 : v0;
            v0 = mn; v1 = mx;
        }
        nxt[t] = v0; nxt[p1] = v1; { unsigned* tm = cur; cur = nxt; nxt = tm; }
        __syncthreads();

        // --- k=1024 remaining: (256,128); (64,32)+tail ---
        v0 = stage_pair(cur, t,  1024, 256, 128);
        v1 = stage_pair(cur, p1, 1024, 256, 128);
        nxt[t] = v0; nxt[p1] = v1; { unsigned* tm = cur; cur = nxt; nxt = tm; }
        __syncthreads();
        v0 = stage_pair(cur, t,  1024, 64, 32); v0 = warp_merge32(v0, t,  1024, 16);
        v1 = stage_pair(cur, p1, 1024, 64, 32); v1 = warp_merge32(v1, p1, 1024, 16);
        nxt[t] = v0; nxt[p1] = v1; { unsigned* tm = cur; cur = nxt; nxt = tm; }
        __syncthreads();
        // cur[] fully sorted; nxt[] stale (reused as s_pos)

        // --- tail section 1: adjacent-pair flags, scan, ranks, scatter ---
        unsigned long long kk = *(const unsigned long long*)&cur[2 * t];
        unsigned k0 = (unsigned)kk, k1s = (unsigned)(kk >> 32);
        int f0 = 0;
        if (t > 0) f0 = (k0 != cur[2 * t - 1]) ? 1 : 0;
        int f1 = (k1s != k0) ? 1 : 0;
        int sflag = f0 + f1;
        int val = sflag;
        #pragma unroll
        for (int o = 1; o < 32; o <<= 1) {
            int n = __shfl_up_sync(0xffffffffu, val, o);
            if (lane >= o) val += n;
        }
        if (lane == 31) s_warp[wid] = val;
        __syncthreads();

        int wp = (lane < 16) ? s_warp[lane] : 0;
        wp = (lane < wid) ? wp : 0;
        #pragma unroll
        for (int o = 16; o > 0; o >>= 1) wp += __shfl_xor_sync(0xffffffffu, wp, o);
        const int excl  = val - sflag + wp;     // exclusive prefix of flags
        const int rank0 = excl + f0;
        const int rank1 = excl + f0 + f1;
        *(unsigned long long*)&s_scan[2 * t] =
            ((unsigned long long)(unsigned)rank1 << 32) | (unsigned)rank0;
        int* s_pos = (int*)nxt;
        const bool is0 = (t == 0) | (f0 != 0);
        if (is0) s_pos[rank0] = 2 * t;
        if (f1)  s_pos[rank1] = 2 * t + 1;
        if (t == NT - 1) s_R = rank1;
        __syncthreads();

        // --- tail section 2: run-length histogram + label update ---
        const int R = s_R;
        if (is0) {
            int end = (rank0 == R) ? 1024 : s_pos[rank0 + 1];
            s_cnt[rank0] += end - 2 * t;
        }
        if (f1) {
            int end = (rank1 == R) ? 1024 : s_pos[rank1 + 1];
            s_cnt[rank1] += end - (2 * t + 1);
        }
        if (it < NITER - 1) {
            int lo0 = 0, lo1 = 0;
            #pragma unroll
            for (int s = 512; s > 0; s >>= 1) {
                if (cur[lo0 + s - 1] < mykey0) lo0 += s;
                if (cur[lo1 + s - 1] < mykey1) lo1 += s;
            }
            mylab0 = s_scan[lo0];
            mylab1 = s_scan[lo1];
            s_lab[t]  = mylab0;
            s_lab[p1] = mylab1;
        }
        __syncthreads();
    }

    // --- feats (global + smem copy for gram) + norm ---
    float c0 = (float)s_cnt[t];
    float c1 = (float)s_cnt[p1];
    float* sf = (float*)s_keyA;
    sf[t] = c0; sf[p1] = c1;
    g_feats[b * NN + t]  = c0;
    g_feats[b * NN + p1] = c1;

    float sq = c0 * c0 + c1 * c1;
    #pragma unroll
    for (int o = 16; o > 0; o >>= 1) sq += __shfl_xor_sync(0xffffffffu, sq, o);
    if (lane == 0) s_warp[wid] = __float_as_int(sq);
    __syncthreads();
    if (t < 32) {
        float x = (t < 16) ? __int_as_float(s_warp[t]) : 0.0f;
        #pragma unroll
        for (int o = 16; o > 0; o >>= 1) x += __shfl_xor_sync(0xffffffffu, x, o);
        if (t == 0) g_dnorm[b] = sqrtf(x);
    }

    // --- grid barrier (monotonic ticket: graph-replay safe) ---
    __threadfence();
    __syncthreads();
    if (t == 0) {
        unsigned ticket = atomicAdd(&g_bar, 1u);
        unsigned target = (ticket / NB + 1u) * NB;
        while (*(volatile unsigned*)&g_bar < target) { }
    }
    __syncthreads();
    __threadfence();

    // --- Phase 2: normalized Gram row b; 4 dots per warp from L2 ---
    const float dn_b = g_dnorm[b];
    const float4* sf4 = (const float4*)sf;
    for (int jj = wid; jj < NB; jj += 16) {
        const float4* fj4 = (const float4*)&g_feats[jj * NN];
        float s = 0.0f;
        #pragma unroll
        for (int k = lane; k < NN / 4; k += 32) {
            float4 a  = sf4[k];
            float4 cc = fj4[k];
            s += a.x * cc.x + a.y * cc.y + a.z * cc.z + a.w * cc.w;
        }
        #pragma unroll
        for (int o = 16; o > 0; o >>= 1) s += __shfl_xor_sync(0xffffffffu, s, o);
        if (lane == 0) out[b * NB + jj] = s / (dn_b * g_dnorm[jj]);
    }
}

extern "C" void kernel_launch(void* const* d_in, const int* in_sizes, int n_in,
                              void* d_out, int out_size)
{
    const int*   esrc = (const int*)d_in[0];
    const int*   edst = (const int*)d_in[1];
    const int*   lab  = (const int*)d_in[2];
    const float* hw   = (const float*)d_in[3];
    const int E = in_sizes[0] / NB;

    const size_t smem_wl = 217088;  // 128K mask + 64K ent + 5x4K arrays
    static bool attr_done = false;
    if (!attr_done) {
        cudaFuncSetAttribute(wl_fused_kernel,
                             cudaFuncAttributeMaxDynamicSharedMemorySize,
                             (int)smem_wl);
        attr_done = true;
    }
    wl_fused_kernel<<<NB, NT, smem_wl>>>(esrc, edst, lab, hw, E, (float*)d_out);
}

// round 15
// speedup vs baseline: 1.0655x; 1.0655x over previous
#include <cuda_runtime.h>

#define NB 64
#define NN 1024
#define NWORDS 32          // NN/32 bitmask words per node row
#define NITER 5

// scratch (no allocations allowed)
__device__ float    g_feats[NB * NN];  // per-graph label histograms (6 stages)
__device__ float    g_dnorm[NB];       // sqrt(dot(feats_b, feats_b))
__device__ unsigned g_bar;             // monotonic grid-barrier ticket counter

// compare-exchange
__device__ __forceinline__ unsigned cex(unsigned a, unsigned b, bool keep_min)
{
    unsigned mn = a < b ? a : b;
    unsigned mx = a < b ? b : a;
    return keep_min ? mn : mx;
}

__device__ __forceinline__ unsigned stage_single(const unsigned* in, int t, int k, int j)
{
    bool asc = ((t & k) == 0);
    return cex(in[t], in[t ^ j], (((t & j) == 0) == asc));
}

// two consecutive stages (j1 then j2=j1/2) fused: 4 reads, 3 cex.
__device__ __forceinline__ unsigned stage_pair(const unsigned* in, int t, int k, int j1, int j2)
{
    bool asc = ((t & k) == 0);
    bool km1 = (((t & j1) == 0) == asc);
    unsigned a  = cex(in[t],      in[t ^ j1],        km1);
    unsigned bb = cex(in[t ^ j2], in[(t ^ j2) ^ j1], km1);
    return cex(a, bb, (((t & j2) == 0) == asc));
}

// intra-warp bitonic merge on 32-bit keys: j = jstart..1 via shuffles
__device__ __forceinline__ unsigned warp_merge32(unsigned v, int t, int k, int jstart)
{
    bool dir = ((t & k) == 0);
    #pragma unroll
    for (int j = jstart; j > 0; j >>= 1) {
        unsigned o = __shfl_xor_sync(0xffffffffu, v, j);
        bool keep_min = (((t & j) == 0) == dir);
        unsigned mn = v < o ? v : o;
        unsigned mx = v < o ? o : v;
        v = keep_min ? mn : mx;
    }
    return v;
}

// -------------------------------------------------------------------------
// FUSED kernel: one block per graph; 64 blocks, 1024 threads (best shape).
// After CSR build, the dead 128KB mask region is repacked as a STRIDED
// entry array ent32[pair][node] (conflict-free warp gathers) when K <= 64.
// Dynamic SMEM (217088 B, opt-in):
//   [0      , 131072) : unsigned smask[32768]   adjacency bits -> ent32 strided
//   [131072 , 196608) : u16 s_ent[32768]        CSR entries (even-aligned runs)
//   [196608 , 200704) : int s_lab[1024]         labels
//   [200704 , 204800) : int s_cnt[1024]         histogram counts
//   [204800 , 208896) : unsigned s_keyA[1024]   sort ping buffer (gram: sf)
//   [208896 , 212992) : unsigned s_keyB[1024]   sort pong buffer (run-pos)
//   [212992 , 217088) : int s_scan[1024]        rank per sorted position
// -------------------------------------------------------------------------
extern "C" __global__ void __launch_bounds__(1024, 1)
wl_fused_kernel(const int* __restrict__ esrc, const int* __restrict__ edst,
                const int* __restrict__ labels0, const float* __restrict__ hw,
                int E, float* __restrict__ out)
{
    extern __shared__ unsigned char s_raw[];
    unsigned*       smask  = (unsigned*)s_raw;                  // 128KB
    unsigned*       ent32s = (unsigned*)s_raw;                  // alias (post-build)
    unsigned short* s_ent  = (unsigned short*)(s_raw + 131072); // 64KB
    int*            s_lab  = (int*)(s_raw + 196608);            // 4KB
    int*            s_cnt  = (int*)(s_raw + 200704);            // 4KB
    unsigned*       s_keyA = (unsigned*)(s_raw + 204800);       // 4KB
    unsigned*       s_keyB = (unsigned*)(s_raw + 208896);       // 4KB
    int*            s_scan = (int*)(s_raw + 212992);            // 4KB
    __shared__ int s_warp[32];

    const int t    = threadIdx.x;
    const int b    = blockIdx.x;
    const int lane = t & 31;
    const int wid  = t >> 5;
    const float w0 = hw[0], w1 = hw[1];

    // --- zero mask + counts ---
    #pragma unroll
    for (int w = 0; w < NWORDS; w++) smask[t + w * 1024] = 0u;
    s_cnt[t] = 0;
    __syncthreads();

    // --- build directed adjacency bitmask (atomicOr dedupes edges) ---
    if ((E & 3) == 0) {
        const int4* s4 = (const int4*)(esrc + (size_t)b * E);
        const int4* d4 = (const int4*)(edst + (size_t)b * E);
        const int n4 = E >> 2;
        for (int i = t; i < n4; i += 1024) {
            int4 s = s4[i];
            int4 d = d4[i];
            atomicOr(&smask[(s.x << 5) + (d.x >> 5)], 1u << (d.x & 31));
            atomicOr(&smask[(s.y << 5) + (d.y >> 5)], 1u << (d.y & 31));
            atomicOr(&smask[(s.z << 5) + (d.z >> 5)], 1u << (d.z & 31));
            atomicOr(&smask[(s.w << 5) + (d.w >> 5)], 1u << (d.w & 31));
        }
    } else {
        for (int e = t; e < E; e += 1024) {
            int s = esrc[b * E + e];
            int d = edst[b * E + e];
            atomicOr(&smask[(s << 5) + (d >> 5)], 1u << (d & 31));
        }
    }

    // --- initial labels + stage-0 histogram (warp-aggregated atomics) ---
    int mylab = labels0[b * NN + t];
    s_lab[t] = mylab;
    {
        unsigned peers = __match_any_sync(0xffffffffu, mylab);
        int leader = __ffs(peers) - 1;
        int cnt    = __popc(peers);
        if (lane == leader) atomicAdd(&s_cnt[mylab], cnt);
    }
    __syncthreads();

    // --- degree (staggered word order -> conflict-free LDS) ---
    int deg = 0;
    #pragma unroll
    for (int wi = 0; wi < NWORDS; wi++) {
        int w = (wi + t) & 31;
        deg += __popc(smask[(t << 5) + w]);
    }
    const int degPad = (deg + 1) & ~1;     // even-align each node's CSR run

    // --- K = max degree, exclusive scan of degPad -> even CSR offsets ---
    int kv = deg;
    #pragma unroll
    for (int o = 16; o > 0; o >>= 1) kv = max(kv, __shfl_xor_sync(0xffffffffu, kv, o));
    int incl = degPad;
    #pragma unroll
    for (int o = 1; o < 32; o <<= 1) {
        int n = __shfl_up_sync(0xffffffffu, incl, o);
        if (lane >= o) incl += n;
    }
    if (lane == 31) { s_warp[wid] = incl; s_scan[wid] = kv; }
    __syncthreads();
    int wpre, K;
    {
        int x = s_warp[lane];
        int xm = (lane < wid) ? x : 0;
        #pragma unroll
        for (int o = 16; o > 0; o >>= 1) xm += __shfl_xor_sync(0xffffffffu, xm, o);
        wpre = xm;
        int m = s_scan[lane & 31];
        #pragma unroll
        for (int o = 16; o > 0; o >>= 1) m = max(m, __shfl_xor_sync(0xffffffffu, m, o));
        K = m;
    }
    const int off = wpre + incl - degPad;  // even exclusive offset
    __syncthreads();

    // --- build compact CSR u16 neighbor entries (once) ---
    {
        int p = off;
        #pragma unroll
        for (int w = 0; w < NWORDS; w++) {
            unsigned m = smask[(t << 5) + w];
            int base = w << 5;
            while (m) {
                int bb = __ffs(m) - 1;
                m &= m - 1;
                s_ent[p++] = (unsigned short)(base + bb);
            }
        }
    }
    __syncthreads();   // mask fully consumed; 128KB region now dead

    // --- repack entries STRIDED into the dead mask region (conflict-free
    //     warp gathers): ent32s[p * 1024 + node] = entries (2p, 2p+1).
    //     Capacity 32 pairs (K <= 64). Uniform fallback keeps correctness.
    const bool strided = (K <= 64);
    const int npair = degPad >> 1;         // u32 pairs for this node
    if (strided) {
        const unsigned* e32c = (const unsigned*)s_ent + (off >> 1);
        for (int p = 0; p < npair; p++)
            ent32s[p * 1024 + t] = e32c[p];   // STS conflict-free (stride 1024)
    }
    __syncthreads();

    const float Kw0 = __fmul_rn((float)K, w0);
    const unsigned* e32base = (const unsigned*)s_ent;

    for (int it = 0; it < NITER; it++) {
        // --- seg = sum of neighbor labels ---
        int seg = 0;
        if (strided) {
            // conflict-free entry stream: lane reads ent32s[p*1024 + t]
            const int nf = deg >> 1;
            #pragma unroll 4
            for (int p = 0; p < nf; p++) {
                unsigned e = ent32s[p * 1024 + t];
                seg += s_lab[e & 0xFFFFu] + s_lab[e >> 16];
            }
            if (deg & 1) {
                unsigned e = ent32s[nf * 1024 + t];
                seg += s_lab[e & 0xFFFFu];      // pair padded; low half valid
            }
        } else {
            const unsigned* e32 = e32base + (off >> 1);
            const int nf = deg >> 1;
            #pragma unroll 4
            for (int n = 0; n < nf; n++) {
                unsigned e = e32[n];
                seg += s_lab[e & 0xFFFFu] + s_lab[e >> 16];
            }
            if (deg & 1) seg += s_lab[s_ent[off + deg - 1]];
        }

        // --- hashed = (K*w0)*lab + w1*(seg+deg-K), no FMA contraction ---
        float h = __fadd_rn(__fmul_rn(Kw0, (float)mylab),
                            __fmul_rn(w1, (float)(seg + deg - K)));
        h = __fadd_rn(h, 0.0f);               // canonicalize -0 -> +0
        unsigned u = __float_as_uint(h);
        u = (u & 0x80000000u) ? ~u : (u | 0x80000000u);   // order-preserving map
        const unsigned mykey = u;
        unsigned v = u;

        // --- warp phase: k = 2..32 in registers ---
        #pragma unroll
        for (int k = 2; k <= 32; k <<= 1)
            v = warp_merge32(v, t, k, k >> 1);

        unsigned* cur = s_keyA;
        unsigned* nxt = s_keyB;
        cur[t] = v;
        __syncthreads();

        // --- k=64 ---
        v = stage_single(cur, t, 64, 32);
        v = warp_merge32(v, t, 64, 16);
        nxt[t] = v; { unsigned* tmp = cur; cur = nxt; nxt = tmp; }
        __syncthreads();

        // --- k=128 ---
        v = stage_pair(cur, t, 128, 64, 32);
        v = warp_merge32(v, t, 128, 16);
        nxt[t] = v; { unsigned* tmp = cur; cur = nxt; nxt = tmp; }
        __syncthreads();

        // --- k=256 ---
        v = stage_pair(cur, t, 256, 128, 64);
        nxt[t] = v; { unsigned* tmp = cur; cur = nxt; nxt = tmp; }
        __syncthreads();
        v = stage_single(cur, t, 256, 32);
        v = warp_merge32(v, t, 256, 16);
        nxt[t] = v; { unsigned* tmp = cur; cur = nxt; nxt = tmp; }
        __syncthreads();

        // --- k=512 ---
        v = stage_pair(cur, t, 512, 256, 128);
        nxt[t] = v; { unsigned* tmp = cur; cur = nxt; nxt = tmp; }
        __syncthreads();
        v = stage_pair(cur, t, 512, 64, 32);
        v = warp_merge32(v, t, 512, 16);
        nxt[t] = v; { unsigned* tmp = cur; cur = nxt; nxt = tmp; }
        __syncthreads();

        // --- k=1024 ---
        v = stage_pair(cur, t, 1024, 512, 256);
        nxt[t] = v; { unsigned* tmp = cur; cur = nxt; nxt = tmp; }
        __syncthreads();
        v = stage_pair(cur, t, 1024, 128, 64);
        nxt[t] = v; { unsigned* tmp = cur; cur = nxt; nxt = tmp; }
        __syncthreads();
        v = stage_single(cur, t, 1024, 32);
        v = warp_merge32(v, t, 1024, 16);
        nxt[t] = v; { unsigned* tmp = cur; cur = nxt; nxt = tmp; }
        __syncthreads();
        // cur[] fully sorted; nxt[] stale keys (reused as s_pos); v = cur[t]

        // --- tail section 1: flags, warp scan, broadcast prefix, scatter ---
        int flag = 0;
        if (t > 0) flag = (v != cur[t - 1]) ? 1 : 0;
        int val = flag;
        #pragma unroll
        for (int o = 1; o < 32; o <<= 1) {
            int n = __shfl_up_sync(0xffffffffu, val, o);
            if (lane >= o) val += n;
        }
        if (lane == 31) s_warp[wid] = val;
        __syncthreads();

        int wp = s_warp[lane];
        wp = (lane < wid) ? wp : 0;
        #pragma unroll
        for (int o = 16; o > 0; o >>= 1) wp += __shfl_xor_sync(0xffffffffu, wp, o);
        const int rank_p = val + wp;
        int* s_pos = (int*)nxt;
        s_scan[t] = rank_p;
        const bool isstart = (t == 0) | (flag != 0);
        if (isstart) s_pos[rank_p] = t;
        __syncthreads();

        // --- tail section 2: run-length histogram + label update ---
        if (isstart) {
            const int R = s_scan[1023];          // max rank this iteration
            int end = (rank_p == R) ? 1024 : s_pos[rank_p + 1];
            s_cnt[rank_p] += end - t;
        }
        if (it < NITER - 1) {
            int lo = 0;
            #pragma unroll
            for (int s = 512; s > 0; s >>= 1)
                if (cur[lo + s - 1] < mykey) lo += s;
            int rank = s_scan[lo];
            s_lab[t] = rank;
            mylab    = rank;
        }
        __syncthreads();
    }

    // --- feats (global + smem copy for gram) + norm ---
    float c = (float)s_cnt[t];
    float* sf = (float*)s_keyA;
    sf[t] = c;
    g_feats[b * NN + t] = c;

    float sq = c * c;
    #pragma unroll
    for (int o = 16; o > 0; o >>= 1) sq += __shfl_xor_sync(0xffffffffu, sq, o);
    if (lane == 0) s_warp[wid] = __float_as_int(sq);
    __syncthreads();
    if (t < 32) {
        float x = __int_as_float(s_warp[t]);
        #pragma unroll
        for (int o = 16; o > 0; o >>= 1) x += __shfl_xor_sync(0xffffffffu, x, o);
        if (t == 0) g_dnorm[b] = sqrtf(x);
    }

    // --- grid barrier (monotonic ticket: graph-replay safe) ---
    __threadfence();
    __syncthreads();
    if (t == 0) {
        unsigned ticket = atomicAdd(&g_bar, 1u);
        unsigned target = (ticket / NB + 1u) * NB;
        while (*(volatile unsigned*)&g_bar < target) { }
    }
    __syncthreads();
    __threadfence();

    // --- Phase 2: normalized Gram row b; 2 dots per warp from L2 ---
    const float dn_b = g_dnorm[b];
    const float4* sf4 = (const float4*)sf;
    for (int jj = wid; jj < NB; jj += 32) {
        const float4* fj4 = (const float4*)&g_feats[jj * NN];
        float s = 0.0f;
        #pragma unroll
        for (int k = lane; k < NN / 4; k += 32) {
            float4 a  = sf4[k];
            float4 cc = fj4[k];
            s += a.x * cc.x + a.y * cc.y + a.z * cc.z + a.w * cc.w;
        }
        #pragma unroll
        for (int o = 16; o > 0; o >>= 1) s += __shfl_xor_sync(0xffffffffu, s, o);
        if (lane == 0) out[b * NB + jj] = s / (dn_b * g_dnorm[jj]);
    }
}

extern "C" void kernel_launch(void* const* d_in, const int* in_sizes, int n_in,
                              void* d_out, int out_size)
{
    const int*   esrc = (const int*)d_in[0];
    const int*   edst = (const int*)d_in[1];
    const int*   lab  = (const int*)d_in[2];
    const float* hw   = (const float*)d_in[3];
    const int E = in_sizes[0] / NB;

    const size_t smem_wl = 217088;  // 128K mask/ent32s + 64K ent + 5x4K arrays
    static bool attr_done = false;
    if (!attr_done) {
        cudaFuncSetAttribute(wl_fused_kernel,
                             cudaFuncAttributeMaxDynamicSharedMemorySize,
                             (int)smem_wl);
        attr_done = true;
    }
    wl_fused_kernel<<<NB, 1024, smem_wl>>>(esrc, edst, lab, hw, E, (float*)d_out);
}